// round 3
// baseline (speedup 1.0000x reference)
#include <cuda_runtime.h>
#include <stdint.h>

#define Bn 2
#define Nn 4096
#define Mn 128
#define RAD 0.1f
#define R2  0.01f

// Output layout (flattened, concatenated in reference return order, all f32)
#define OFF_IDXS 0
#define OFF_NBR  (Bn*Nn)                       // 8192
#define OFF_LOCS (OFF_NBR + Bn*Nn*Mn)          // 1056768
#define OFF_DATA (OFF_LOCS + Bn*Nn*3)          // 1081344

// Scratch (no allocations allowed)
__device__ uint32_t g_keys[Bn*Nn];
__device__ float4   g_locs[Bn*Nn];   // sorted locs, .w = |p|^2

// ---------------------------------------------------------------------------
// Kernel 1: per-batch bounds + cell ids + packed stable sort keys
// Replicates reference grid math with explicit rn intrinsics (no fma fusion).
// ---------------------------------------------------------------------------
__global__ void k_cellids(const float* __restrict__ locs) {
    int b = blockIdx.x;
    const float* L = locs + (size_t)b * Nn * 3;
    __shared__ float smin[3][1024];
    __shared__ float smax[3][1024];
    int t = threadIdx.x;

    float mn0 = 1e30f, mn1 = 1e30f, mn2 = 1e30f;
    float mx0 = -1e30f, mx1 = -1e30f, mx2 = -1e30f;
    for (int i = t; i < Nn; i += 1024) {
        float x = L[i*3+0], y = L[i*3+1], z = L[i*3+2];
        mn0 = fminf(mn0, x); mx0 = fmaxf(mx0, x);
        mn1 = fminf(mn1, y); mx1 = fmaxf(mx1, y);
        mn2 = fminf(mn2, z); mx2 = fmaxf(mx2, z);
    }
    smin[0][t] = mn0; smin[1][t] = mn1; smin[2][t] = mn2;
    smax[0][t] = mx0; smax[1][t] = mx1; smax[2][t] = mx2;
    __syncthreads();
    for (int s = 512; s > 0; s >>= 1) {
        if (t < s) {
            #pragma unroll
            for (int d = 0; d < 3; d++) {
                smin[d][t] = fminf(smin[d][t], smin[d][t+s]);
                smax[d][t] = fmaxf(smax[d][t], smax[d][t+s]);
            }
        }
        __syncthreads();
    }

    __shared__ float lo[3], gdm1[3];
    __shared__ int   strd[3];
    if (t == 0) {
        float gdv[3];
        #pragma unroll
        for (int d = 0; d < 3; d++) {
            float l = smin[d][0], u = smax[d][0];
            // grid_dims = ceil(clip((u-l)/RADIUS, 0, 96))
            float r = __fdiv_rn(__fsub_rn(u, l), RAD);
            r = fminf(fmaxf(r, 0.0f), 96.0f);
            float gdf = ceilf(r);
            // lower = center - grid_dims*RADIUS*0.5
            float c = __fmul_rn(__fadd_rn(l, u), 0.5f);
            lo[d] = __fsub_rn(c, __fmul_rn(__fmul_rn(gdf, RAD), 0.5f));
            float gd = fmaxf(gdf, 1.0f);
            gdv[d] = gd;
            gdm1[d] = gd - 1.0f;
        }
        int g1 = (int)gdv[1], g2 = (int)gdv[2];
        strd[0] = g1 * g2; strd[1] = g2; strd[2] = 1;
    }
    __syncthreads();

    for (int i = t; i < Nn; i += 1024) {
        int flat = 0;
        #pragma unroll
        for (int d = 0; d < 3; d++) {
            float c = floorf(__fdiv_rn(__fsub_rn(L[i*3+d], lo[d]), RAD));
            c = fminf(fmaxf(c, 0.0f), gdm1[d]);
            flat += (int)c * strd[d];
        }
        g_keys[b*Nn + i] = ((uint32_t)flat << 12) | (uint32_t)i;
    }
}

// ---------------------------------------------------------------------------
// Kernel 2: bitonic sort of 4096 uint32 keys per batch (keys unique -> stable
// order by (cell, original index)). One block per batch, 16KB SMEM.
// ---------------------------------------------------------------------------
__global__ void k_sort() {
    __shared__ uint32_t s[Nn];
    uint32_t* gk = g_keys + blockIdx.x * Nn;
    for (int i = threadIdx.x; i < Nn; i += 1024) s[i] = gk[i];
    __syncthreads();
    for (int k = 2; k <= Nn; k <<= 1) {
        for (int j = k >> 1; j > 0; j >>= 1) {
            for (int i = threadIdx.x; i < Nn; i += 1024) {
                int l = i ^ j;
                if (l > i) {
                    uint32_t a = s[i], c = s[l];
                    bool up = ((i & k) == 0);
                    if ((a > c) == up) { s[i] = c; s[l] = a; }
                }
            }
            __syncthreads();
        }
    }
    for (int i = threadIdx.x; i < Nn; i += 1024) gk[i] = s[i];
}

// ---------------------------------------------------------------------------
// Kernel 3: gather by sorted order; write idxs, locs_s, data_s outputs and
// stash float4{x,y,z,|p|^2} for the neighbor pass (sq computed ONCE, matching
// reference's single sq computation used on both sides of d2).
// ---------------------------------------------------------------------------
__global__ void k_gather(const float* __restrict__ locs,
                         const float* __restrict__ data,
                         float* __restrict__ out) {
    int gid = blockIdx.x * blockDim.x + threadIdx.x;
    if (gid >= Bn * Nn) return;
    int b = gid >> 12;
    int ord = (int)(g_keys[gid] & 4095u);

    const float* lp = locs + (size_t)(b*Nn + ord) * 3;
    float x = lp[0], y = lp[1], z = lp[2];
    float sq = __fadd_rn(__fadd_rn(__fmul_rn(x, x), __fmul_rn(y, y)),
                         __fmul_rn(z, z));
    g_locs[gid] = make_float4(x, y, z, sq);

    out[OFF_IDXS + gid] = (float)ord;
    float* lout = out + OFF_LOCS + (size_t)gid * 3;
    lout[0] = x; lout[1] = y; lout[2] = z;

    const float4* dp = (const float4*)(data + (size_t)(b*Nn + ord) * 16);
    float4* dq = (float4*)(out + OFF_DATA + (size_t)gid * 16);
    #pragma unroll
    for (int q = 0; q < 4; q++) dq[q] = dp[q];
}

// ---------------------------------------------------------------------------
// Kernel 4: neighbor lists. One warp per sorted particle; all 4096 sorted locs
// staged in 64KB dynamic SMEM. Ballot+prefix-popc realizes "first 128
// in-radius indices, ascending" exactly (== reference's stable 0/1 argsort).
// d2 = (sq_i + sq_j) - 2*dot, same formula/order as the reference, rn-exact.
// ---------------------------------------------------------------------------
__global__ void k_neighbors(float* __restrict__ out) {
    extern __shared__ float4 sh[];
    int b    = blockIdx.x >> 7;     // 128 tiles of 32 particles per batch
    int tile = blockIdx.x & 127;
    const float4* gl = g_locs + b * Nn;
    for (int i = threadIdx.x; i < Nn; i += 1024) sh[i] = gl[i];
    __syncthreads();

    int warp = threadIdx.x >> 5;
    int lane = threadIdx.x & 31;
    int i = tile * 32 + warp;
    float4 me = sh[i];
    float* nout = out + OFF_NBR + (size_t)(b*Nn + i) * Mn;

    int count = 0;
    for (int j0 = 0; j0 < Nn; j0 += 32) {
        float4 o = sh[j0 + lane];
        float dot = __fadd_rn(__fadd_rn(__fmul_rn(me.x, o.x),
                                        __fmul_rn(me.y, o.y)),
                              __fmul_rn(me.z, o.z));
        float d2 = __fsub_rn(__fadd_rn(me.w, o.w), __fmul_rn(2.0f, dot));
        bool m = (d2 <= R2);
        unsigned bal = __ballot_sync(0xffffffffu, m);
        if (m) {
            int pos = count + __popc(bal & ((1u << lane) - 1u));
            if (pos < Mn) nout[pos] = (float)(j0 + lane);
        }
        count += __popc(bal);
        if (count >= Mn) break;
    }
    for (int s = min(count, Mn) + lane; s < Mn; s += 32) nout[s] = -1.0f;
}

// ---------------------------------------------------------------------------
extern "C" void kernel_launch(void* const* d_in, const int* in_sizes, int n_in,
                              void* d_out, int out_size) {
    const float* locs = (const float*)d_in[0];
    const float* data = (const float*)d_in[1];
    float* out = (float*)d_out;

    cudaFuncSetAttribute(k_neighbors,
                         cudaFuncAttributeMaxDynamicSharedMemorySize, 65536);

    k_cellids<<<Bn, 1024>>>(locs);
    k_sort<<<Bn, 1024>>>();
    k_gather<<<(Bn*Nn + 255) / 256, 256>>>(locs, data, out);
    k_neighbors<<<Bn * (Nn / 32), 1024, 65536>>>(out);
}

// round 4
// speedup vs baseline: 2.2572x; 2.2572x over previous
#include <cuda_runtime.h>
#include <cub/cub.cuh>
#include <stdint.h>

#define Bn 2
#define Nn 4096
#define Mn 128
#define RAD 0.1f
#define R2  0.01f

// Output layout (flattened, concatenated in reference return order, all f32)
#define OFF_IDXS 0
#define OFF_NBR  (Bn*Nn)                       // 8192
#define OFF_LOCS (OFF_NBR + Bn*Nn*Mn)          // 1056768
#define OFF_DATA (OFF_LOCS + Bn*Nn*3)          // 1081344

// Scratch (no runtime allocations allowed)
__device__ uint32_t g_keys[Bn*Nn];   // sorted (cell<<12 | idx) per batch
__device__ float4   g_locs[Bn*Nn];   // sorted locs, .w = |p|^2
__device__ int4     g_grid[Bn];      // {g0, g1, g2, unused}

// ---------------------------------------------------------------------------
// Kernel 1 (fused): bounds -> grid math (rn-exact, reference-identical) ->
// packed stable keys -> CUB block radix sort. One block per batch.
// ---------------------------------------------------------------------------
typedef cub::BlockRadixSort<uint32_t, 1024, 4> Sorter;

__global__ __launch_bounds__(1024, 1) void k_prep(const float* __restrict__ locs) {
    int b = blockIdx.x;
    const float* L = locs + (size_t)b * Nn * 3;
    int t = threadIdx.x, lane = t & 31, warp = t >> 5;

    __shared__ float wmn[3][32], wmx[3][32];
    __shared__ float s_lo[3], s_gdm1[3];
    __shared__ int   s_strd[3], s_endbit, s_g[3];
    __shared__ typename Sorter::TempStorage ts;

    // per-thread min/max over 4 strided elements
    float mn[3] = {1e30f, 1e30f, 1e30f};
    float mx[3] = {-1e30f, -1e30f, -1e30f};
    for (int i = t; i < Nn; i += 1024) {
        #pragma unroll
        for (int d = 0; d < 3; d++) {
            float v = L[i*3+d];
            mn[d] = fminf(mn[d], v); mx[d] = fmaxf(mx[d], v);
        }
    }
    #pragma unroll
    for (int o = 16; o; o >>= 1) {
        #pragma unroll
        for (int d = 0; d < 3; d++) {
            mn[d] = fminf(mn[d], __shfl_xor_sync(0xffffffffu, mn[d], o));
            mx[d] = fmaxf(mx[d], __shfl_xor_sync(0xffffffffu, mx[d], o));
        }
    }
    if (lane == 0) {
        #pragma unroll
        for (int d = 0; d < 3; d++) { wmn[d][warp] = mn[d]; wmx[d][warp] = mx[d]; }
    }
    __syncthreads();
    if (t < 32) {
        #pragma unroll
        for (int d = 0; d < 3; d++) { mn[d] = wmn[d][t]; mx[d] = wmx[d][t]; }
        #pragma unroll
        for (int o = 16; o; o >>= 1) {
            #pragma unroll
            for (int d = 0; d < 3; d++) {
                mn[d] = fminf(mn[d], __shfl_xor_sync(0xffffffffu, mn[d], o));
                mx[d] = fmaxf(mx[d], __shfl_xor_sync(0xffffffffu, mx[d], o));
            }
        }
        if (t == 0) {
            float gdv[3];
            #pragma unroll
            for (int d = 0; d < 3; d++) {
                float l = mn[d], u = mx[d];
                float r = __fdiv_rn(__fsub_rn(u, l), RAD);
                r = fminf(fmaxf(r, 0.0f), 96.0f);
                float gdf = ceilf(r);
                float c = __fmul_rn(__fadd_rn(l, u), 0.5f);
                s_lo[d] = __fsub_rn(c, __fmul_rn(__fmul_rn(gdf, RAD), 0.5f));
                float gd = fmaxf(gdf, 1.0f);
                gdv[d] = gd;
                s_gdm1[d] = gd - 1.0f;
            }
            int g0 = (int)gdv[0], g1 = (int)gdv[1], g2 = (int)gdv[2];
            s_g[0] = g0; s_g[1] = g1; s_g[2] = g2;
            s_strd[0] = g1 * g2; s_strd[1] = g2; s_strd[2] = 1;
            int ncells = g0 * g1 * g2;
            int cellbits = (ncells <= 1) ? 0 : (32 - __clz(ncells - 1));
            s_endbit = 12 + cellbits;
            g_grid[b] = make_int4(g0, g1, g2, 0);
        }
    }
    __syncthreads();

    // compute this thread's 4 blocked keys
    uint32_t tk[4];
    #pragma unroll
    for (int k = 0; k < 4; k++) {
        int i = t * 4 + k;
        int flat = 0;
        #pragma unroll
        for (int d = 0; d < 3; d++) {
            float c = floorf(__fdiv_rn(__fsub_rn(L[i*3+d], s_lo[d]), RAD));
            c = fminf(fmaxf(c, 0.0f), s_gdm1[d]);
            flat += (int)c * s_strd[d];
        }
        tk[k] = ((uint32_t)flat << 12) | (uint32_t)i;
    }
    int endbit = s_endbit;
    __syncthreads();

    Sorter(ts).Sort(tk, 0, endbit);

    uint32_t* gk = g_keys + b * Nn;
    #pragma unroll
    for (int k = 0; k < 4; k++) gk[t * 4 + k] = tk[k];
}

// ---------------------------------------------------------------------------
// Kernel 2: gather by sorted order; write idxs, locs_s, data_s and stash
// float4{x,y,z,|p|^2} (sq computed ONCE, used on both sides of d2).
// ---------------------------------------------------------------------------
__global__ void k_gather(const float* __restrict__ locs,
                         const float* __restrict__ data,
                         float* __restrict__ out) {
    int gid = blockIdx.x * blockDim.x + threadIdx.x;
    if (gid >= Bn * Nn) return;
    int b = gid >> 12;
    int ord = (int)(g_keys[gid] & 4095u);

    const float* lp = locs + (size_t)(b*Nn + ord) * 3;
    float x = lp[0], y = lp[1], z = lp[2];
    float sq = __fadd_rn(__fadd_rn(__fmul_rn(x, x), __fmul_rn(y, y)),
                         __fmul_rn(z, z));
    g_locs[gid] = make_float4(x, y, z, sq);

    out[OFF_IDXS + gid] = (float)ord;
    float* lout = out + OFF_LOCS + (size_t)gid * 3;
    lout[0] = x; lout[1] = y; lout[2] = z;

    const float4* dp = (const float4*)(data + (size_t)(b*Nn + ord) * 16);
    float4* dq = (float4*)(out + OFF_DATA + (size_t)gid * 16);
    #pragma unroll
    for (int q = 0; q < 4; q++) dq[q] = dp[q];
}

// ---------------------------------------------------------------------------
// Kernel 3: neighbor lists with cell pruning. One warp per sorted particle.
// 9 (dx,dy) segments found by parallel binary search on sorted keys; segments
// visited in ascending cell-id (== ascending sorted index) order, realizing
// the reference's "first 128 in-radius, ascending" exactly.
// ---------------------------------------------------------------------------
__global__ void k_neighbors(float* __restrict__ out) {
    extern __shared__ char smem[];
    float4*   shl = (float4*)smem;                 // 65536 B
    uint32_t* shk = (uint32_t*)(smem + Nn * 16);   // 16384 B
    int b    = blockIdx.x >> 7;
    int tile = blockIdx.x & 127;
    const float4*   gl = g_locs + b * Nn;
    const uint32_t* gk = g_keys + b * Nn;
    for (int i = threadIdx.x; i < Nn; i += 1024) { shl[i] = gl[i]; shk[i] = gk[i]; }
    __syncthreads();

    int4 G = g_grid[b];
    int g0 = G.x, g1 = G.y, g2 = G.z;

    int warp = threadIdx.x >> 5;
    int lane = threadIdx.x & 31;
    int i = tile * 32 + warp;

    uint32_t mykey = shk[i];
    int cell = (int)(mykey >> 12);
    int cz = cell % g2;
    int t2 = cell / g2;
    int cy = t2 % g1;
    int cx = t2 / g1;

    // lanes 0..17: binary search the 9 segment bounds (2 per segment)
    int res = 0;
    if (lane < 18) {
        int s  = lane >> 1;
        int dx = s / 3 - 1, dy = s % 3 - 1;
        int nx = cx + dx, ny = cy + dy;
        if (nx >= 0 && nx < g0 && ny >= 0 && ny < g1) {
            int base = (nx * g1 + ny) * g2;
            int zlo = max(cz - 1, 0), zhi = min(cz + 1, g2 - 1);
            uint32_t target = ((uint32_t)((lane & 1) ? (base + zhi + 1)
                                                     : (base + zlo))) << 12;
            int lo = 0, hi = Nn;
            while (lo < hi) {
                int mid = (lo + hi) >> 1;
                if (shk[mid] < target) lo = mid + 1; else hi = mid;
            }
            res = lo;
        }
    }

    float4 me = shl[i];
    float* nout = out + OFF_NBR + (size_t)(b*Nn + i) * Mn;
    unsigned lt = (1u << lane) - 1u;

    int count = 0;
    #pragma unroll 1
    for (int s = 0; s < 9; s++) {
        int lo = __shfl_sync(0xffffffffu, res, 2*s);
        int hi = __shfl_sync(0xffffffffu, res, 2*s + 1);
        for (int j0 = lo; j0 < hi; j0 += 32) {
            int j = j0 + lane;
            bool m = false;
            if (j < hi) {
                float4 o = shl[j];
                float dot = __fadd_rn(__fadd_rn(__fmul_rn(me.x, o.x),
                                                __fmul_rn(me.y, o.y)),
                                      __fmul_rn(me.z, o.z));
                float d2 = __fsub_rn(__fadd_rn(me.w, o.w), __fmul_rn(2.0f, dot));
                m = (d2 <= R2);
            }
            unsigned bal = __ballot_sync(0xffffffffu, m);
            if (m) {
                int pos = count + __popc(bal & lt);
                if (pos < Mn) nout[pos] = (float)j;
            }
            count += __popc(bal);
            if (count >= Mn) goto fill;
        }
    }
fill:
    for (int p = min(count, Mn) + lane; p < Mn; p += 32) nout[p] = -1.0f;
}

// ---------------------------------------------------------------------------
extern "C" void kernel_launch(void* const* d_in, const int* in_sizes, int n_in,
                              void* d_out, int out_size) {
    const float* locs = (const float*)d_in[0];
    const float* data = (const float*)d_in[1];
    float* out = (float*)d_out;

    cudaFuncSetAttribute(k_neighbors,
                         cudaFuncAttributeMaxDynamicSharedMemorySize,
                         Nn * 16 + Nn * 4);

    k_prep<<<Bn, 1024>>>(locs);
    k_gather<<<(Bn*Nn + 255) / 256, 256>>>(locs, data, out);
    k_neighbors<<<Bn * (Nn / 32), 1024, Nn * 16 + Nn * 4>>>(out);
}

// round 7
// speedup vs baseline: 2.8135x; 1.2465x over previous
#include <cuda_runtime.h>
#include <cub/cub.cuh>
#include <stdint.h>

#define Bn 2
#define Nn 4096
#define Mn 128
#define RAD 0.1f
#define R2  0.01f

// Output layout (flattened, concatenated in reference return order, all f32)
#define OFF_IDXS 0
#define OFF_NBR  (Bn*Nn)                       // 8192
#define OFF_LOCS (OFF_NBR + Bn*Nn*Mn)          // 1056768
#define OFF_DATA (OFF_LOCS + Bn*Nn*3)          // 1081344

// Scratch (no runtime allocations allowed)
__device__ uint32_t g_keys[Bn*Nn];   // sorted (cell<<12 | idx) per batch
__device__ float4   g_locs[Bn*Nn];   // sorted locs, .w = |p|^2
__device__ int4     g_grid[Bn];      // {g0, g1, g2, unused}

// ---------------------------------------------------------------------------
// Kernel 1 (fused): bounds -> grid math (rn-exact, reference-identical) ->
// packed stable keys -> CUB block radix sort over CELL BITS ONLY.
// Keys are generated in ascending-index blocked order; BlockRadixSort's
// prefix-sum ranking is stable per pass, so sorting bits [12, 12+cellbits)
// preserves index order within equal cells == reference stable argsort.
// RADIX_BITS=5 -> ceil(10/5)=2 passes for this input (vs 6 before).
// ---------------------------------------------------------------------------
typedef cub::BlockRadixSort<uint32_t, 1024, 4, cub::NullType, 5> Sorter;

__global__ __launch_bounds__(1024, 1) void k_prep(const float* __restrict__ locs) {
    int b = blockIdx.x;
    const float* L = locs + (size_t)b * Nn * 3;
    int t = threadIdx.x, lane = t & 31, warp = t >> 5;

    __shared__ float wmn[3][32], wmx[3][32];
    __shared__ float s_lo[3], s_gdm1[3];
    __shared__ int   s_strd[3], s_endbit;
    __shared__ typename Sorter::TempStorage ts;

    float mn[3] = {1e30f, 1e30f, 1e30f};
    float mx[3] = {-1e30f, -1e30f, -1e30f};
    for (int i = t; i < Nn; i += 1024) {
        #pragma unroll
        for (int d = 0; d < 3; d++) {
            float v = L[i*3+d];
            mn[d] = fminf(mn[d], v); mx[d] = fmaxf(mx[d], v);
        }
    }
    #pragma unroll
    for (int o = 16; o; o >>= 1) {
        #pragma unroll
        for (int d = 0; d < 3; d++) {
            mn[d] = fminf(mn[d], __shfl_xor_sync(0xffffffffu, mn[d], o));
            mx[d] = fmaxf(mx[d], __shfl_xor_sync(0xffffffffu, mx[d], o));
        }
    }
    if (lane == 0) {
        #pragma unroll
        for (int d = 0; d < 3; d++) { wmn[d][warp] = mn[d]; wmx[d][warp] = mx[d]; }
    }
    __syncthreads();
    if (t < 32) {
        #pragma unroll
        for (int d = 0; d < 3; d++) { mn[d] = wmn[d][t]; mx[d] = wmx[d][t]; }
        #pragma unroll
        for (int o = 16; o; o >>= 1) {
            #pragma unroll
            for (int d = 0; d < 3; d++) {
                mn[d] = fminf(mn[d], __shfl_xor_sync(0xffffffffu, mn[d], o));
                mx[d] = fmaxf(mx[d], __shfl_xor_sync(0xffffffffu, mx[d], o));
            }
        }
        if (t == 0) {
            float gdv[3];
            #pragma unroll
            for (int d = 0; d < 3; d++) {
                float l = mn[d], u = mx[d];
                float r = __fdiv_rn(__fsub_rn(u, l), RAD);
                r = fminf(fmaxf(r, 0.0f), 96.0f);
                float gdf = ceilf(r);
                float c = __fmul_rn(__fadd_rn(l, u), 0.5f);
                s_lo[d] = __fsub_rn(c, __fmul_rn(__fmul_rn(gdf, RAD), 0.5f));
                float gd = fmaxf(gdf, 1.0f);
                gdv[d] = gd;
                s_gdm1[d] = gd - 1.0f;
            }
            int g0 = (int)gdv[0], g1 = (int)gdv[1], g2 = (int)gdv[2];
            s_strd[0] = g1 * g2; s_strd[1] = g2; s_strd[2] = 1;
            int ncells = g0 * g1 * g2;
            int cellbits = (ncells <= 1) ? 0 : (32 - __clz(ncells - 1));
            s_endbit = 12 + cellbits;
            g_grid[b] = make_int4(g0, g1, g2, 0);
        }
    }
    __syncthreads();

    // this thread's 4 blocked keys (ascending index across blocked layout)
    uint32_t tk[4];
    #pragma unroll
    for (int k = 0; k < 4; k++) {
        int i = t * 4 + k;
        int flat = 0;
        #pragma unroll
        for (int d = 0; d < 3; d++) {
            float c = floorf(__fdiv_rn(__fsub_rn(L[i*3+d], s_lo[d]), RAD));
            c = fminf(fmaxf(c, 0.0f), s_gdm1[d]);
            flat += (int)c * s_strd[d];
        }
        tk[k] = ((uint32_t)flat << 12) | (uint32_t)i;
    }
    int endbit = s_endbit;
    __syncthreads();

    if (endbit > 12) {
        Sorter(ts).Sort(tk, 12, endbit);   // cell bits only; stable passes
    }

    uint32_t* gk = g_keys + b * Nn;
    #pragma unroll
    for (int k = 0; k < 4; k++) gk[t * 4 + k] = tk[k];
}

// ---------------------------------------------------------------------------
// Kernel 2: gather by sorted order; write idxs, locs_s, data_s and stash
// float4{x,y,z,|p|^2} (sq computed ONCE, used on both sides of d2).
// ---------------------------------------------------------------------------
__global__ void k_gather(const float* __restrict__ locs,
                         const float* __restrict__ data,
                         float* __restrict__ out) {
    int gid = blockIdx.x * blockDim.x + threadIdx.x;
    if (gid >= Bn * Nn) return;
    int b = gid >> 12;
    int ord = (int)(g_keys[gid] & 4095u);

    const float* lp = locs + (size_t)(b*Nn + ord) * 3;
    float x = lp[0], y = lp[1], z = lp[2];
    float sq = __fadd_rn(__fadd_rn(__fmul_rn(x, x), __fmul_rn(y, y)),
                         __fmul_rn(z, z));
    g_locs[gid] = make_float4(x, y, z, sq);

    out[OFF_IDXS + gid] = (float)ord;
    float* lout = out + OFF_LOCS + (size_t)gid * 3;
    lout[0] = x; lout[1] = y; lout[2] = z;

    const float4* dp = (const float4*)(data + (size_t)(b*Nn + ord) * 16);
    float4* dq = (float4*)(out + OFF_DATA + (size_t)gid * 16);
    #pragma unroll
    for (int q = 0; q < 4; q++) dq[q] = dp[q];
}

// ---------------------------------------------------------------------------
// Kernel 3: neighbor lists with cell pruning. One warp per sorted particle.
// 9 (dx,dy) segments found by parallel binary search on sorted keys; segments
// visited in ascending cell-id (== ascending sorted index) order, realizing
// the reference's "first 128 in-radius, ascending" exactly.
// ---------------------------------------------------------------------------
__global__ void k_neighbors(float* __restrict__ out) {
    extern __shared__ char smem[];
    float4*   shl = (float4*)smem;                 // 65536 B
    uint32_t* shk = (uint32_t*)(smem + Nn * 16);   // 16384 B
    int b    = blockIdx.x >> 7;
    int tile = blockIdx.x & 127;
    const float4*   gl = g_locs + b * Nn;
    const uint32_t* gk = g_keys + b * Nn;
    for (int i = threadIdx.x; i < Nn; i += 1024) { shl[i] = gl[i]; shk[i] = gk[i]; }
    __syncthreads();

    int4 G = g_grid[b];
    int g0 = G.x, g1 = G.y, g2 = G.z;

    int warp = threadIdx.x >> 5;
    int lane = threadIdx.x & 31;
    int i = tile * 32 + warp;

    uint32_t mykey = shk[i];
    int cell = (int)(mykey >> 12);
    int cz = cell % g2;
    int t2 = cell / g2;
    int cy = t2 % g1;
    int cx = t2 / g1;

    // lanes 0..17: binary search the 9 segment bounds (2 per segment)
    int res = 0;
    if (lane < 18) {
        int s  = lane >> 1;
        int dx = s / 3 - 1, dy = s % 3 - 1;
        int nx = cx + dx, ny = cy + dy;
        if (nx >= 0 && nx < g0 && ny >= 0 && ny < g1) {
            int base = (nx * g1 + ny) * g2;
            int zlo = max(cz - 1, 0), zhi = min(cz + 1, g2 - 1);
            uint32_t target = ((uint32_t)((lane & 1) ? (base + zhi + 1)
                                                     : (base + zlo))) << 12;
            int lo = 0, hi = Nn;
            while (lo < hi) {
                int mid = (lo + hi) >> 1;
                if (shk[mid] < target) lo = mid + 1; else hi = mid;
            }
            res = lo;
        }
    }

    float4 me = shl[i];
    float* nout = out + OFF_NBR + (size_t)(b*Nn + i) * Mn;
    unsigned lt = (1u << lane) - 1u;

    int count = 0;
    #pragma unroll 1
    for (int s = 0; s < 9; s++) {
        int lo = __shfl_sync(0xffffffffu, res, 2*s);
        int hi = __shfl_sync(0xffffffffu, res, 2*s + 1);
        for (int j0 = lo; j0 < hi; j0 += 32) {
            int j = j0 + lane;
            bool m = false;
            if (j < hi) {
                float4 o = shl[j];
                float dot = __fadd_rn(__fadd_rn(__fmul_rn(me.x, o.x),
                                                __fmul_rn(me.y, o.y)),
                                      __fmul_rn(me.z, o.z));
                float d2 = __fsub_rn(__fadd_rn(me.w, o.w), __fmul_rn(2.0f, dot));
                m = (d2 <= R2);
            }
            unsigned bal = __ballot_sync(0xffffffffu, m);
            if (m) {
                int pos = count + __popc(bal & lt);
                if (pos < Mn) nout[pos] = (float)j;
            }
            count += __popc(bal);
            if (count >= Mn) goto fill;
        }
    }
fill:
    for (int p = min(count, Mn) + lane; p < Mn; p += 32) nout[p] = -1.0f;
}

// ---------------------------------------------------------------------------
extern "C" void kernel_launch(void* const* d_in, const int* in_sizes, int n_in,
                              void* d_out, int out_size) {
    const float* locs = (const float*)d_in[0];
    const float* data = (const float*)d_in[1];
    float* out = (float*)d_out;

    cudaFuncSetAttribute(k_neighbors,
                         cudaFuncAttributeMaxDynamicSharedMemorySize,
                         Nn * 16 + Nn * 4);

    k_prep<<<Bn, 1024>>>(locs);
    k_gather<<<(Bn*Nn + 255) / 256, 256>>>(locs, data, out);
    k_neighbors<<<Bn * (Nn / 32), 1024, Nn * 16 + Nn * 4>>>(out);
}